// round 8
// baseline (speedup 1.0000x reference)
#include <cuda_runtime.h>
#include <cuda_fp16.h>
#include <stdint.h>
#include <math.h>

// ---------------------------------------------------------------------------
// SimpleMamba via warp-level mma.sync fp16 GEMM (single product).
//   R8: interleaved B layout [(n>>4)*48 + mat*16 + (n&15)] so each warp's
//       48 cols hold lam/del/u of the SAME 16 channels -> in-register gates,
//       no 192-wide SMEM roundtrip. SMEM 80KB -> 2 CTAs/SM.
//   512 threads (16 warps, warp tile 32x48), BK=32, 4-stage cp.async ring.
//   combine: s = P*s + S over 32 chunks + head projections -> 24 floats.
// ---------------------------------------------------------------------------

#define DM    1024
#define KD    1024
#define BM    128
#define BNC   64
#define BK    32
#define NKT   (KD / BK)      // 32
#define NCHUNK 32
#define ASTR  66             // alpha/drive tile col stride

#define STAGE_BYTES 20480    // Ah 8K + Bh 12K
#define OFF_BH  8192
#define NSTAGE 4
#define SMEM_TOTAL (NSTAGE * STAGE_BYTES)   // 81920 >= scan tile 67584

#define NTH 512

// ---------------- device scratch ----------------
__device__ __align__(128) __half g_Ah[32768u * 1024u];
__device__ __align__(128) __half g_Bh[3u * 1024u * 1024u];   // interleaved rows
__device__ float g_P[8 * NCHUNK * DM];
__device__ float g_S[8 * NCHUNK * DM];

// ---------------- helpers ----------------
static __device__ __forceinline__ uint32_t smem_u32(const void* p) {
    uint32_t a;
    asm("{ .reg .u64 t; cvta.to.shared.u64 t, %1; cvt.u32.u64 %0, t; }" : "=r"(a) : "l"(p));
    return a;
}
static __device__ __forceinline__ uint32_t sw64(uint32_t o) { return o ^ ((o >> 3) & 0x30); }

static __device__ __forceinline__ void cp16(uint32_t dst, const void* src) {
    asm volatile("cp.async.cg.shared.global [%0], [%1], 16;" :: "r"(dst), "l"(src) : "memory");
}
static __device__ __forceinline__ void cp_commit() {
    asm volatile("cp.async.commit_group;" ::: "memory");
}
static __device__ __forceinline__ void ldsm4(uint32_t* r, uint32_t addr) {
    asm volatile("ldmatrix.sync.aligned.m8n8.x4.shared.b16 {%0,%1,%2,%3}, [%4];"
        : "=r"(r[0]), "=r"(r[1]), "=r"(r[2]), "=r"(r[3]) : "r"(addr));
}
static __device__ __forceinline__ void mma_f16(float* c, const uint32_t* a,
                                               uint32_t b0, uint32_t b1) {
    asm volatile("mma.sync.aligned.m16n8k16.row.col.f32.f16.f16.f32 "
        "{%0,%1,%2,%3}, {%4,%5,%6,%7}, {%8,%9}, {%0,%1,%2,%3};"
        : "+f"(c[0]), "+f"(c[1]), "+f"(c[2]), "+f"(c[3])
        : "r"(a[0]), "r"(a[1]), "r"(a[2]), "r"(a[3]), "r"(b0), "r"(b1));
}

// cheap softplus: max(z,0) + log(1 + e^{-|z|})
static __device__ __forceinline__ float softplus_f(float z) {
    return fmaxf(z, 0.0f) + __logf(1.0f + __expf(-fabsf(z)));
}

// ---------------- prep kernels ----------------
__global__ void __launch_bounds__(256) conv_x_kernel(const float* __restrict__ x) {
    size_t i = (size_t)blockIdx.x * 256 + threadIdx.x;   // float4 index
    float4 v = ((const float4*)x)[i];
    __half2 H0, H1;
    H0.x = __float2half(v.x); H0.y = __float2half(v.y);
    H1.x = __float2half(v.z); H1.y = __float2half(v.w);
    ((__half2*)g_Ah)[2 * i] = H0;
    ((__half2*)g_Ah)[2 * i + 1] = H1;
}

// W[k][n] -> interleaved rows: row = (n>>4)*48 + mat*16 + (n&15), [row][k] fp16
__global__ void __launch_bounds__(256) conv_w_kernel(const float* __restrict__ Wl,
                                                     const float* __restrict__ Wd,
                                                     const float* __restrict__ Wb) {
    const float* W = (blockIdx.z == 0) ? Wl : (blockIdx.z == 1) ? Wd : Wb;
    __shared__ float ts[32][33];
    const int k0 = blockIdx.y * 32, n0 = blockIdx.x * 32;
    const int tx = threadIdx.x, ty = threadIdx.y;
#pragma unroll
    for (int i = 0; i < 4; i++) {
        int k = ty + i * 8;
        ts[k][tx] = W[(size_t)(k0 + k) * DM + n0 + tx];
    }
    __syncthreads();
    const int mat = blockIdx.z;
#pragma unroll
    for (int i = 0; i < 4; i++) {
        int n = n0 + ty + i * 8;
        int row = (n >> 4) * 48 + mat * 16 + (n & 15);
        g_Bh[(size_t)row * KD + k0 + tx] = __float2half(ts[tx][ty + i * 8]);
    }
}

// ---------------- GEMM + scan ----------------
static __device__ __forceinline__ void load_stage(int kt, int buf, int tid, int R, int C,
                                                  uint32_t sb) {
    const uint32_t st = sb + buf * STAGE_BYTES;
    // A: 128 rows x 4 chunks = 512 -> 1/thread
    {
        int row = tid >> 2, q = tid & 3;
        size_t g = ((size_t)(R + row) << 10) + kt * BK + q * 8;
        cp16(st + sw64((uint32_t)(row * 64 + q * 16)), g_Ah + g);
    }
    // B: 192 interleaved rows x 4 chunks = 768 -> 1.5/thread
    const int Crow = C * 3;   // first interleaved row for this CTA
#pragma unroll
    for (int i = 0; i < 2; i++) {
        int c = i * NTH + tid;
        if (c < 768) {
            int row = c >> 2, q = c & 3;
            size_t g = ((size_t)(Crow + row) << 10) + kt * BK + q * 8;
            cp16(st + OFF_BH + sw64((uint32_t)(row * 64 + q * 16)), g_Bh + g);
        }
    }
    cp_commit();
}

__global__ void __launch_bounds__(NTH, 2)
mamba_gemm_mma(const float* __restrict__ pbl, const float* __restrict__ pbd,
               const float* __restrict__ pbb) {
    extern __shared__ char smem[];
    const uint32_t sb = smem_u32(smem);
    const int tid = threadIdx.x;
    const int warp = tid >> 5;
    const int lane = tid & 31;
    const int R = blockIdx.y * BM;
    const int C = blockIdx.x * BNC;
    const int wm = warp >> 2;      // 0..3  (m block of 32)
    const int wn = warp & 3;       // 0..3  (16-channel group)

    float acc[2][6][4];
#pragma unroll
    for (int i = 0; i < 2; i++)
#pragma unroll
        for (int j = 0; j < 6; j++)
#pragma unroll
            for (int k = 0; k < 4; k++) acc[i][j][k] = 0.0f;

    const int a_row_l = wm * 32 + (lane & 15);
    const int a_cb = (lane >> 4) * 16;
    const int b_row_l = wn * 48 + ((lane >> 4) & 1) * 8 + (lane & 7);
    const int b_cb = ((lane >> 3) & 1) * 16;

    load_stage(0, 0, tid, R, C, sb);
    load_stage(1, 1, tid, R, C, sb);
    load_stage(2, 2, tid, R, C, sb);

    for (int kt = 0; kt < NKT; kt++) {
        asm volatile("cp.async.wait_group 2;" ::: "memory");
        __syncthreads();
        if (kt + 3 < NKT) load_stage(kt + 3, (kt + 3) & 3, tid, R, C, sb);

        const uint32_t st = sb + (kt & 3) * STAGE_BYTES;
#pragma unroll
        for (int ks2 = 0; ks2 < 2; ks2++) {
            const int kb = ks2 * 32;
            uint32_t Ah[2][4], Bh[3][4];
#pragma unroll
            for (int mt = 0; mt < 2; mt++)
                ldsm4(Ah[mt], st + sw64((uint32_t)((a_row_l + mt * 16) * 64 + kb + a_cb)));
#pragma unroll
            for (int nt = 0; nt < 3; nt++)
                ldsm4(Bh[nt], st + OFF_BH + sw64((uint32_t)((b_row_l + nt * 16) * 64 + kb + b_cb)));
#pragma unroll
            for (int mt = 0; mt < 2; mt++)
#pragma unroll
                for (int nt = 0; nt < 3; nt++) {
                    mma_f16(acc[mt][2 * nt],     Ah[mt], Bh[nt][0], Bh[nt][1]);
                    mma_f16(acc[mt][2 * nt + 1], Ah[mt], Bh[nt][2], Bh[nt][3]);
                }
        }
    }
    asm volatile("cp.async.wait_group 0;" ::: "memory");
    __syncthreads();   // all warps done with stage buffers before aliasing

    // ---- in-register gates -> alpha/drive SMEM tiles ----
    // warp wn's 48 cols = [lam ch0..15 | del ch0..15 | u ch0..15] of channels
    // wn*16 + (0..15). Thread's cols within group: g*8 + 2*(lane&3) + e.
    float* SA = (float*)smem;                 // [128][ASTR]
    float* SD = SA + BM * ASTR;               // [128][ASTR]
    {
        const int q2 = 2 * (lane & 3);
        // biases for this thread's 4 channels (g in {0,1}, e in {0,1})
        float bl_[2][2], bd_[2][2], bb_[2][2];
#pragma unroll
        for (int g = 0; g < 2; g++)
#pragma unroll
            for (int e = 0; e < 2; e++) {
                const int gc = C + wn * 16 + g * 8 + q2 + e;
                bl_[g][e] = __ldg(pbl + gc);
                bd_[g][e] = __ldg(pbd + gc);
                bb_[g][e] = __ldg(pbb + gc);
            }
#pragma unroll
        for (int mt = 0; mt < 2; mt++)
#pragma unroll
            for (int h = 0; h < 2; h++) {
                const int row = wm * 32 + mt * 16 + (lane >> 2) + 8 * h;
#pragma unroll
                for (int g = 0; g < 2; g++) {
                    float a0, a1, d0, d1;
#pragma unroll
                    for (int e = 0; e < 2; e++) {
                        float lam = softplus_f(acc[mt][g][2 * h + e]     + bl_[g][e]);
                        float de  = softplus_f(acc[mt][2 + g][2 * h + e] + bd_[g][e]);
                        float u   = acc[mt][4 + g][2 * h + e] + bb_[g][e];
                        float al  = __expf(-de * lam);
                        float dr  = de * u;
                        if (e == 0) { a0 = al; d0 = dr; } else { a1 = al; d1 = dr; }
                    }
                    const int ch = wn * 16 + g * 8 + q2;
                    *(float2*)&SA[row * ASTR + ch] = make_float2(a0, a1);
                    *(float2*)&SD[row * ASTR + ch] = make_float2(d0, d1);
                }
            }
    }
    __syncthreads();

    // ---- split scan: 128 threads, 2 per channel (64-row halves) ----
    __shared__ float sP[2][BNC], sS[2][BNC];
    if (tid < 2 * BNC) {
        const int ch = tid & 63;
        const int hf = tid >> 6;
        float s = 0.0f, P = 1.0f;
        const int t0 = hf * 64;
#pragma unroll 8
        for (int t = t0; t < t0 + 64; t++) {
            float a = SA[t * ASTR + ch];
            float d = SD[t * ASTR + ch];
            s = fmaf(a, s, d);
            P *= a;
        }
        sP[hf][ch] = P;
        sS[hf][ch] = s;
    }
    __syncthreads();
    if (tid < BNC) {
        const float P = sP[0][tid] * sP[1][tid];
        const float s = fmaf(sP[1][tid], sS[0][tid], sS[1][tid]);
        const int bidx = R >> 12;
        const int chunk = (R >> 7) & 31;
        const int idx = ((bidx * NCHUNK + chunk) << 10) + C + tid;
        g_P[idx] = P;
        g_S[idx] = s;
    }
}

// ---------------- combine chunks + head projections ----------------
__global__ void __launch_bounds__(1024)
combine_kernel(const float* __restrict__ W_par, const float* __restrict__ b_par,
               const float* __restrict__ W_add, const float* __restrict__ b_add,
               float* __restrict__ out)
{
    const int b = blockIdx.x;
    const int d = threadIdx.x;

    float s = 0.0f;
#pragma unroll
    for (int c = 0; c < NCHUNK; c++) {
        const int idx = ((b * NCHUNK + c) << 10) + d;
        s = fmaf(g_P[idx], s, g_S[idx]);
    }

    float v0 = s * W_par[2 * d];
    float v1 = s * W_par[2 * d + 1];
    float v2 = s * W_add[d];

#pragma unroll
    for (int o = 16; o > 0; o >>= 1) {
        v0 += __shfl_xor_sync(0xffffffffu, v0, o);
        v1 += __shfl_xor_sync(0xffffffffu, v1, o);
        v2 += __shfl_xor_sync(0xffffffffu, v2, o);
    }

    __shared__ float r0[32], r1[32], r2[32];
    const int lane = d & 31, wid = d >> 5;
    if (lane == 0) { r0[wid] = v0; r1[wid] = v1; r2[wid] = v2; }
    __syncthreads();
    if (wid == 0) {
        v0 = r0[lane]; v1 = r1[lane]; v2 = r2[lane];
#pragma unroll
        for (int o = 16; o > 0; o >>= 1) {
            v0 += __shfl_xor_sync(0xffffffffu, v0, o);
            v1 += __shfl_xor_sync(0xffffffffu, v1, o);
            v2 += __shfl_xor_sync(0xffffffffu, v2, o);
        }
        if (lane == 0) {
            out[2 * b]     = v0 + b_par[0];
            out[2 * b + 1] = v1 + b_par[1];
            out[16 + b]    = v2 + b_add[0];
        }
    }
}

extern "C" void kernel_launch(void* const* d_in, const int* in_sizes, int n_in,
                              void* d_out, int out_size)
{
    const float* x  = (const float*)d_in[0];
    const float* Wl = (const float*)d_in[1];
    const float* bl = (const float*)d_in[2];
    const float* Wd = (const float*)d_in[3];
    const float* bd = (const float*)d_in[4];
    const float* Wb = (const float*)d_in[5];
    const float* bb = (const float*)d_in[6];
    const float* Wp = (const float*)d_in[7];
    const float* bp = (const float*)d_in[8];
    const float* Wa = (const float*)d_in[9];
    const float* ba = (const float*)d_in[10];
    float* out = (float*)d_out;

    cudaFuncSetAttribute(mamba_gemm_mma,
                         cudaFuncAttributeMaxDynamicSharedMemorySize, SMEM_TOTAL);

    conv_x_kernel<<<32768, 256>>>(x);
    conv_w_kernel<<<dim3(32, 32, 3), dim3(32, 8)>>>(Wl, Wd, Wb);
    mamba_gemm_mma<<<dim3(16, 256), NTH, SMEM_TOTAL>>>(bl, bd, bb);
    combine_kernel<<<8, 1024>>>(Wp, bp, Wa, ba, out);
}

// round 9
// speedup vs baseline: 2.0844x; 2.0844x over previous
#include <cuda_runtime.h>
#include <cuda_fp16.h>
#include <stdint.h>
#include <math.h>

// ---------------------------------------------------------------------------
// SimpleMamba via warp-level mma.sync fp16 GEMM (single product).
//   R9 = R7 (682us) + interleaved-B in-register gates + fragment ping-pong:
//   prefetch next k16 slice's ldmatrix while current slice's HMMAs issue.
//   B rows interleaved: row = (n>>4)*48 + mat*16 + (n&15) so each warp's
//   48 cols are lam/del/u of the SAME 16 channels.
//   512 threads (16 warps, warp tile 32x48), BK=64, 3-stage cp.async ring.
// ---------------------------------------------------------------------------

#define DM    1024
#define KD    1024
#define BM    128
#define BNC   64
#define BK    64
#define NKT   (KD / BK)      // 16
#define NCHUNK 32
#define ASTR  66             // alpha/drive tile col stride

#define STAGE_BYTES 40960    // Ah 16K + Bh 24K
#define OFF_BH  16384
#define NSTAGE 3
#define SMEM_TOTAL (NSTAGE * STAGE_BYTES)   // 122880 (>= scan tile 67584)

#define NTH 512

// ---------------- device scratch ----------------
__device__ __align__(128) __half g_Ah[32768u * 1024u];
__device__ __align__(128) __half g_Bh[3u * 1024u * 1024u];   // interleaved rows
__device__ float g_P[8 * NCHUNK * DM];
__device__ float g_S[8 * NCHUNK * DM];

// ---------------- helpers ----------------
static __device__ __forceinline__ uint32_t smem_u32(const void* p) {
    uint32_t a;
    asm("{ .reg .u64 t; cvta.to.shared.u64 t, %1; cvt.u32.u64 %0, t; }" : "=r"(a) : "l"(p));
    return a;
}
static __device__ __forceinline__ uint32_t sw128(uint32_t o) { return o ^ ((o >> 3) & 0x70); }

static __device__ __forceinline__ void cp16(uint32_t dst, const void* src) {
    asm volatile("cp.async.cg.shared.global [%0], [%1], 16;" :: "r"(dst), "l"(src) : "memory");
}
static __device__ __forceinline__ void cp_commit() {
    asm volatile("cp.async.commit_group;" ::: "memory");
}
static __device__ __forceinline__ void ldsm4(uint32_t* r, uint32_t addr) {
    asm volatile("ldmatrix.sync.aligned.m8n8.x4.shared.b16 {%0,%1,%2,%3}, [%4];"
        : "=r"(r[0]), "=r"(r[1]), "=r"(r[2]), "=r"(r[3]) : "r"(addr));
}
static __device__ __forceinline__ void mma_f16(float* c, const uint32_t* a,
                                               uint32_t b0, uint32_t b1) {
    asm volatile("mma.sync.aligned.m16n8k16.row.col.f32.f16.f16.f32 "
        "{%0,%1,%2,%3}, {%4,%5,%6,%7}, {%8,%9}, {%0,%1,%2,%3};"
        : "+f"(c[0]), "+f"(c[1]), "+f"(c[2]), "+f"(c[3])
        : "r"(a[0]), "r"(a[1]), "r"(a[2]), "r"(a[3]), "r"(b0), "r"(b1));
}

// cheap softplus: max(z,0) + log(1 + e^{-|z|})
static __device__ __forceinline__ float softplus_f(float z) {
    return fmaxf(z, 0.0f) + __logf(1.0f + __expf(-fabsf(z)));
}

// ---------------- prep kernels ----------------
__global__ void __launch_bounds__(256) conv_x_kernel(const float* __restrict__ x) {
    size_t i = (size_t)blockIdx.x * 256 + threadIdx.x;   // float4 index
    float4 v = ((const float4*)x)[i];
    __half2 H0, H1;
    H0.x = __float2half(v.x); H0.y = __float2half(v.y);
    H1.x = __float2half(v.z); H1.y = __float2half(v.w);
    ((__half2*)g_Ah)[2 * i] = H0;
    ((__half2*)g_Ah)[2 * i + 1] = H1;
}

// W[k][n] -> interleaved rows: row = (n>>4)*48 + mat*16 + (n&15), [row][k] fp16
__global__ void __launch_bounds__(256) conv_w_kernel(const float* __restrict__ Wl,
                                                     const float* __restrict__ Wd,
                                                     const float* __restrict__ Wb) {
    const float* W = (blockIdx.z == 0) ? Wl : (blockIdx.z == 1) ? Wd : Wb;
    __shared__ float ts[32][33];
    const int k0 = blockIdx.y * 32, n0 = blockIdx.x * 32;
    const int tx = threadIdx.x, ty = threadIdx.y;
#pragma unroll
    for (int i = 0; i < 4; i++) {
        int k = ty + i * 8;
        ts[k][tx] = W[(size_t)(k0 + k) * DM + n0 + tx];
    }
    __syncthreads();
    const int mat = blockIdx.z;
#pragma unroll
    for (int i = 0; i < 4; i++) {
        int n = n0 + ty + i * 8;
        int row = (n >> 4) * 48 + mat * 16 + (n & 15);
        g_Bh[(size_t)row * KD + k0 + tx] = __float2half(ts[tx][ty + i * 8]);
    }
}

// ---------------- GEMM + scan ----------------
static __device__ __forceinline__ void load_stage(int kt, int buf, int tid, int R, int Crow,
                                                  uint32_t sb) {
    const uint32_t st = sb + buf * STAGE_BYTES;
    // A: 128 rows x 8 16B-chunks = 1024 -> 2/thread
#pragma unroll
    for (int i = 0; i < 2; i++) {
        int c = i * NTH + tid;
        int row = c >> 3, q = c & 7;
        size_t g = ((size_t)(R + row) << 10) + kt * BK + q * 8;
        cp16(st + sw128((uint32_t)(row * 128 + q * 16)), g_Ah + g);
    }
    // B: 192 interleaved rows x 8 chunks = 1536 -> 3/thread
#pragma unroll
    for (int i = 0; i < 3; i++) {
        int c = i * NTH + tid;
        int row = c >> 3, q = c & 7;
        size_t g = ((size_t)(Crow + row) << 10) + kt * BK + q * 8;
        cp16(st + OFF_BH + sw128((uint32_t)(row * 128 + q * 16)), g_Bh + g);
    }
    cp_commit();
}

static __device__ __forceinline__ void frag_load(uint32_t A[2][4], uint32_t B[3][4],
                                                 uint32_t st, int kb,
                                                 int a_row_l, int a_cb,
                                                 int b_row_l, int b_cb) {
#pragma unroll
    for (int mt = 0; mt < 2; mt++)
        ldsm4(A[mt], st + sw128((uint32_t)((a_row_l + mt * 16) * 128 + kb + a_cb)));
#pragma unroll
    for (int nt = 0; nt < 3; nt++)
        ldsm4(B[nt], st + OFF_BH + sw128((uint32_t)((b_row_l + nt * 16) * 128 + kb + b_cb)));
}

static __device__ __forceinline__ void do_mma(float acc[2][6][4],
                                              uint32_t A[2][4], uint32_t B[3][4]) {
#pragma unroll
    for (int mt = 0; mt < 2; mt++)
#pragma unroll
        for (int nt = 0; nt < 3; nt++) {
            mma_f16(acc[mt][2 * nt],     A[mt], B[nt][0], B[nt][1]);
            mma_f16(acc[mt][2 * nt + 1], A[mt], B[nt][2], B[nt][3]);
        }
}

__global__ void __launch_bounds__(NTH)
mamba_gemm_mma(const float* __restrict__ pbl, const float* __restrict__ pbd,
               const float* __restrict__ pbb) {
    extern __shared__ char smem[];
    const uint32_t sb = smem_u32(smem);
    const int tid = threadIdx.x;
    const int warp = tid >> 5;
    const int lane = tid & 31;
    const int R = blockIdx.y * BM;
    const int C = blockIdx.x * BNC;
    const int Crow = C * 3;        // first interleaved B row for this CTA
    const int wm = warp >> 2;      // 0..3  (m block of 32)
    const int wn = warp & 3;       // 0..3  (16-channel group)

    float acc[2][6][4];
#pragma unroll
    for (int i = 0; i < 2; i++)
#pragma unroll
        for (int j = 0; j < 6; j++)
#pragma unroll
            for (int k = 0; k < 4; k++) acc[i][j][k] = 0.0f;

    const int a_row_l = wm * 32 + (lane & 15);
    const int a_cb = (lane >> 4) * 16;
    const int b_row_l = wn * 48 + ((lane >> 4) & 1) * 8 + (lane & 7);
    const int b_cb = ((lane >> 3) & 1) * 16;

    uint32_t Af[2][2][4], Bf[2][3][4];   // ping-pong fragment buffers

    load_stage(0, 0, tid, R, Crow, sb);
    load_stage(1, 1, tid, R, Crow, sb);
    asm volatile("cp.async.wait_group 1;" ::: "memory");   // stage 0 ready
    __syncthreads();
    frag_load(Af[0], Bf[0], sb, 0, a_row_l, a_cb, b_row_l, b_cb);

    for (int kt = 0; kt < NKT; kt++) {
        const uint32_t st = sb + (kt % 3) * STAGE_BYTES;
        if (kt + 2 < NKT) load_stage(kt + 2, (kt + 2) % 3, tid, R, Crow, sb);
#pragma unroll
        for (int ks = 0; ks < 4; ks++) {
            const int cur = ks & 1, nxt = cur ^ 1;
            if (ks < 3) {
                frag_load(Af[nxt], Bf[nxt], st, (ks + 1) * 32,
                          a_row_l, a_cb, b_row_l, b_cb);
            } else if (kt + 1 < NKT) {
                if (kt + 2 < NKT)
                    asm volatile("cp.async.wait_group 1;" ::: "memory");
                else
                    asm volatile("cp.async.wait_group 0;" ::: "memory");
                __syncthreads();
                frag_load(Af[nxt], Bf[nxt], sb + ((kt + 1) % 3) * STAGE_BYTES, 0,
                          a_row_l, a_cb, b_row_l, b_cb);
            }
            do_mma(acc, Af[cur], Bf[cur]);
        }
    }
    __syncthreads();   // all ldsm done before aliasing stage buffers

    // ---- in-register gates -> alpha/drive SMEM tiles ----
    float* SA = (float*)smem;                 // [128][ASTR]
    float* SD = SA + BM * ASTR;               // [128][ASTR]
    {
        const int q2 = 2 * (lane & 3);
        float bl_[2][2], bd_[2][2], bb_[2][2];
#pragma unroll
        for (int g = 0; g < 2; g++)
#pragma unroll
            for (int e = 0; e < 2; e++) {
                const int gc = C + wn * 16 + g * 8 + q2 + e;
                bl_[g][e] = __ldg(pbl + gc);
                bd_[g][e] = __ldg(pbd + gc);
                bb_[g][e] = __ldg(pbb + gc);
            }
#pragma unroll
        for (int mt = 0; mt < 2; mt++)
#pragma unroll
            for (int h = 0; h < 2; h++) {
                const int row = wm * 32 + mt * 16 + (lane >> 2) + 8 * h;
#pragma unroll
                for (int g = 0; g < 2; g++) {
                    float a0, a1, d0, d1;
#pragma unroll
                    for (int e = 0; e < 2; e++) {
                        float lam = softplus_f(acc[mt][g][2 * h + e]     + bl_[g][e]);
                        float de  = softplus_f(acc[mt][2 + g][2 * h + e] + bd_[g][e]);
                        float u   = acc[mt][4 + g][2 * h + e] + bb_[g][e];
                        float al  = __expf(-de * lam);
                        float dr  = de * u;
                        if (e == 0) { a0 = al; d0 = dr; } else { a1 = al; d1 = dr; }
                    }
                    const int ch = wn * 16 + g * 8 + q2;
                    *(float2*)&SA[row * ASTR + ch] = make_float2(a0, a1);
                    *(float2*)&SD[row * ASTR + ch] = make_float2(d0, d1);
                }
            }
    }
    __syncthreads();

    // ---- split scan: 128 threads, 2 per channel (64-row halves) ----
    __shared__ float sP[2][BNC], sS[2][BNC];
    if (tid < 2 * BNC) {
        const int ch = tid & 63;
        const int hf = tid >> 6;
        float s = 0.0f, P = 1.0f;
        const int t0 = hf * 64;
#pragma unroll 8
        for (int t = t0; t < t0 + 64; t++) {
            float a = SA[t * ASTR + ch];
            float d = SD[t * ASTR + ch];
            s = fmaf(a, s, d);
            P *= a;
        }
        sP[hf][ch] = P;
        sS[hf][ch] = s;
    }
    __syncthreads();
    if (tid < BNC) {
        const float P = sP[0][tid] * sP[1][tid];
        const float s = fmaf(sP[1][tid], sS[0][tid], sS[1][tid]);
        const int bidx = R >> 12;
        const int chunk = (R >> 7) & 31;
        const int idx = ((bidx * NCHUNK + chunk) << 10) + C + tid;
        g_P[idx] = P;
        g_S[idx] = s;
    }
}

// ---------------- combine chunks + head projections ----------------
__global__ void __launch_bounds__(1024)
combine_kernel(const float* __restrict__ W_par, const float* __restrict__ b_par,
               const float* __restrict__ W_add, const float* __restrict__ b_add,
               float* __restrict__ out)
{
    const int b = blockIdx.x;
    const int d = threadIdx.x;

    float s = 0.0f;
#pragma unroll
    for (int c = 0; c < NCHUNK; c++) {
        const int idx = ((b * NCHUNK + c) << 10) + d;
        s = fmaf(g_P[idx], s, g_S[idx]);
    }

    float v0 = s * W_par[2 * d];
    float v1 = s * W_par[2 * d + 1];
    float v2 = s * W_add[d];

#pragma unroll
    for (int o = 16; o > 0; o >>= 1) {
        v0 += __shfl_xor_sync(0xffffffffu, v0, o);
        v1 += __shfl_xor_sync(0xffffffffu, v1, o);
        v2 += __shfl_xor_sync(0xffffffffu, v2, o);
    }

    __shared__ float r0[32], r1[32], r2[32];
    const int lane = d & 31, wid = d >> 5;
    if (lane == 0) { r0[wid] = v0; r1[wid] = v1; r2[wid] = v2; }
    __syncthreads();
    if (wid == 0) {
        v0 = r0[lane]; v1 = r1[lane]; v2 = r2[lane];
#pragma unroll
        for (int o = 16; o > 0; o >>= 1) {
            v0 += __shfl_xor_sync(0xffffffffu, v0, o);
            v1 += __shfl_xor_sync(0xffffffffu, v1, o);
            v2 += __shfl_xor_sync(0xffffffffu, v2, o);
        }
        if (lane == 0) {
            out[2 * b]     = v0 + b_par[0];
            out[2 * b + 1] = v1 + b_par[1];
            out[16 + b]    = v2 + b_add[0];
        }
    }
}

extern "C" void kernel_launch(void* const* d_in, const int* in_sizes, int n_in,
                              void* d_out, int out_size)
{
    const float* x  = (const float*)d_in[0];
    const float* Wl = (const float*)d_in[1];
    const float* bl = (const float*)d_in[2];
    const float* Wd = (const float*)d_in[3];
    const float* bd = (const float*)d_in[4];
    const float* Wb = (const float*)d_in[5];
    const float* bb = (const float*)d_in[6];
    const float* Wp = (const float*)d_in[7];
    const float* bp = (const float*)d_in[8];
    const float* Wa = (const float*)d_in[9];
    const float* ba = (const float*)d_in[10];
    float* out = (float*)d_out;

    cudaFuncSetAttribute(mamba_gemm_mma,
                         cudaFuncAttributeMaxDynamicSharedMemorySize, SMEM_TOTAL);

    conv_x_kernel<<<32768, 256>>>(x);
    conv_w_kernel<<<dim3(32, 32, 3), dim3(32, 8)>>>(Wl, Wd, Wb);
    mamba_gemm_mma<<<dim3(16, 256), NTH, SMEM_TOTAL>>>(bl, bd, bb);
    combine_kernel<<<8, 1024>>>(Wp, bp, Wa, ba, out);
}

// round 10
// speedup vs baseline: 2.0916x; 1.0034x over previous
#include <cuda_runtime.h>
#include <cuda_fp16.h>
#include <stdint.h>
#include <math.h>

// ---------------------------------------------------------------------------
// SimpleMamba via warp-level mma.sync fp16 GEMM (single product).
//   R10 = R9 + persistent CTAs (148), each sweeping ~27 tiles with a
//   CONTINUOUS cp.async stage stream across tile boundaries: next tile's
//   loads fly while current tile's epilogue (gates+scan) runs. Scan tile
//   moved to dedicated SMEM (no ring aliasing). 512 thr, BK=64, 3-ring.
// ---------------------------------------------------------------------------

#define DM    1024
#define KD    1024
#define BM    128
#define BNC   64
#define BK    64
#define KTPT  16             // k-stages per tile (1024/64)
#define NCHUNK 32
#define ASTR  66
#define NTILE 4096           // 256 mt x 16 nt
#define NCTA  148

#define STAGE_BYTES 40960    // Ah 16K + Bh 24K
#define OFF_BH  16384
#define SCAN_OFF (3 * STAGE_BYTES)            // 122880
#define SMEM_TOTAL (SCAN_OFF + 2 * BM * ASTR * 4)  // 122880 + 67584 = 190464

#define NTH 512

// ---------------- device scratch ----------------
__device__ __align__(128) __half g_Ah[32768u * 1024u];
__device__ __align__(128) __half g_Bh[3u * 1024u * 1024u];   // interleaved rows
__device__ float g_P[8 * NCHUNK * DM];
__device__ float g_S[8 * NCHUNK * DM];

// ---------------- helpers ----------------
static __device__ __forceinline__ uint32_t smem_u32(const void* p) {
    uint32_t a;
    asm("{ .reg .u64 t; cvta.to.shared.u64 t, %1; cvt.u32.u64 %0, t; }" : "=r"(a) : "l"(p));
    return a;
}
static __device__ __forceinline__ uint32_t sw128(uint32_t o) { return o ^ ((o >> 3) & 0x70); }

static __device__ __forceinline__ void cp16(uint32_t dst, const void* src) {
    asm volatile("cp.async.cg.shared.global [%0], [%1], 16;" :: "r"(dst), "l"(src) : "memory");
}
static __device__ __forceinline__ void ldsm4(uint32_t* r, uint32_t addr) {
    asm volatile("ldmatrix.sync.aligned.m8n8.x4.shared.b16 {%0,%1,%2,%3}, [%4];"
        : "=r"(r[0]), "=r"(r[1]), "=r"(r[2]), "=r"(r[3]) : "r"(addr));
}
static __device__ __forceinline__ void mma_f16(float* c, const uint32_t* a,
                                               uint32_t b0, uint32_t b1) {
    asm volatile("mma.sync.aligned.m16n8k16.row.col.f32.f16.f16.f32 "
        "{%0,%1,%2,%3}, {%4,%5,%6,%7}, {%8,%9}, {%0,%1,%2,%3};"
        : "+f"(c[0]), "+f"(c[1]), "+f"(c[2]), "+f"(c[3])
        : "r"(a[0]), "r"(a[1]), "r"(a[2]), "r"(a[3]), "r"(b0), "r"(b1));
}

static __device__ __forceinline__ float softplus_f(float z) {
    return fmaxf(z, 0.0f) + __logf(1.0f + __expf(-fabsf(z)));
}

// ---------------- prep kernels ----------------
__global__ void __launch_bounds__(256) conv_x_kernel(const float* __restrict__ x) {
    size_t i = (size_t)blockIdx.x * 256 + threadIdx.x;
    float4 v = ((const float4*)x)[i];
    __half2 H0, H1;
    H0.x = __float2half(v.x); H0.y = __float2half(v.y);
    H1.x = __float2half(v.z); H1.y = __float2half(v.w);
    ((__half2*)g_Ah)[2 * i] = H0;
    ((__half2*)g_Ah)[2 * i + 1] = H1;
}

// W[k][n] -> interleaved rows: row = (n>>4)*48 + mat*16 + (n&15), [row][k] fp16
__global__ void __launch_bounds__(256) conv_w_kernel(const float* __restrict__ Wl,
                                                     const float* __restrict__ Wd,
                                                     const float* __restrict__ Wb) {
    const float* W = (blockIdx.z == 0) ? Wl : (blockIdx.z == 1) ? Wd : Wb;
    __shared__ float ts[32][33];
    const int k0 = blockIdx.y * 32, n0 = blockIdx.x * 32;
    const int tx = threadIdx.x, ty = threadIdx.y;
#pragma unroll
    for (int i = 0; i < 4; i++) {
        int k = ty + i * 8;
        ts[k][tx] = W[(size_t)(k0 + k) * DM + n0 + tx];
    }
    __syncthreads();
    const int mat = blockIdx.z;
#pragma unroll
    for (int i = 0; i < 4; i++) {
        int n = n0 + ty + i * 8;
        int row = (n >> 4) * 48 + mat * 16 + (n & 15);
        g_Bh[(size_t)row * KD + k0 + tx] = __float2half(ts[tx][ty + i * 8]);
    }
}

// ---------------- GEMM + scan (persistent) ----------------
// global stage s of this CTA: tile = cta + NCTA*(s>>4), kt = s&15
static __device__ __forceinline__ void load_stage(int s, int cta, int tid, uint32_t sb) {
    const int tile = cta + NCTA * (s >> 4);
    const int kt = s & 15;
    const int R = (tile >> 4) * BM;
    const int Crow = (tile & 15) * 192;
    const uint32_t st = sb + (s % 3) * STAGE_BYTES;
    // A: 128 rows x 8 16B-chunks = 1024 -> 2/thread
#pragma unroll
    for (int i = 0; i < 2; i++) {
        int c = i * NTH + tid;
        int row = c >> 3, q = c & 7;
        size_t g = ((size_t)(R + row) << 10) + kt * BK + q * 8;
        cp16(st + sw128((uint32_t)(row * 128 + q * 16)), g_Ah + g);
    }
    // B: 192 interleaved rows x 8 chunks = 1536 -> 3/thread
#pragma unroll
    for (int i = 0; i < 3; i++) {
        int c = i * NTH + tid;
        int row = c >> 3, q = c & 7;
        size_t g = ((size_t)(Crow + row) << 10) + kt * BK + q * 8;
        cp16(st + OFF_BH + sw128((uint32_t)(row * 128 + q * 16)), g_Bh + g);
    }
    asm volatile("cp.async.commit_group;" ::: "memory");
}

static __device__ __forceinline__ void frag_load(uint32_t A[2][4], uint32_t B[3][4],
                                                 uint32_t st, int kb,
                                                 int a_row_l, int a_cb,
                                                 int b_row_l, int b_cb) {
#pragma unroll
    for (int mt = 0; mt < 2; mt++)
        ldsm4(A[mt], st + sw128((uint32_t)((a_row_l + mt * 16) * 128 + kb + a_cb)));
#pragma unroll
    for (int nt = 0; nt < 3; nt++)
        ldsm4(B[nt], st + OFF_BH + sw128((uint32_t)((b_row_l + nt * 16) * 128 + kb + b_cb)));
}

static __device__ __forceinline__ void do_mma(float acc[2][6][4],
                                              uint32_t A[2][4], uint32_t B[3][4]) {
#pragma unroll
    for (int mt = 0; mt < 2; mt++)
#pragma unroll
        for (int nt = 0; nt < 3; nt++) {
            mma_f16(acc[mt][2 * nt],     A[mt], B[nt][0], B[nt][1]);
            mma_f16(acc[mt][2 * nt + 1], A[mt], B[nt][2], B[nt][3]);
        }
}

__global__ void __launch_bounds__(NTH)
mamba_gemm_mma(const float* __restrict__ pbl, const float* __restrict__ pbd,
               const float* __restrict__ pbb) {
    extern __shared__ char smem[];
    const uint32_t sb = smem_u32(smem);
    const int tid = threadIdx.x;
    const int warp = tid >> 5;
    const int lane = tid & 31;
    const int cta = blockIdx.x;
    const int wm = warp >> 2;
    const int wn = warp & 3;

    const int ntiles = (NTILE - cta + NCTA - 1) / NCTA;
    const int G = ntiles * KTPT;

    float* SA = (float*)(smem + SCAN_OFF);          // [128][ASTR]
    float* SD = SA + BM * ASTR;
    __shared__ float sP[2][BNC], sS[2][BNC];

    float acc[2][6][4];
#pragma unroll
    for (int i = 0; i < 2; i++)
#pragma unroll
        for (int j = 0; j < 6; j++)
#pragma unroll
            for (int k = 0; k < 4; k++) acc[i][j][k] = 0.0f;

    const int a_row_l = wm * 32 + (lane & 15);
    const int a_cb = (lane >> 4) * 16;
    const int b_row_l = wn * 48 + ((lane >> 4) & 1) * 8 + (lane & 7);
    const int b_cb = ((lane >> 3) & 1) * 16;
    const int q2 = 2 * (lane & 3);

    uint32_t Af[2][2][4], Bf[2][3][4];

    load_stage(0, cta, tid, sb);
    load_stage(1, cta, tid, sb);
    asm volatile("cp.async.wait_group 1;" ::: "memory");
    __syncthreads();
    frag_load(Af[0], Bf[0], sb, 0, a_row_l, a_cb, b_row_l, b_cb);

    for (int s = 0; s < G; s++) {
        const uint32_t st = sb + (s % 3) * STAGE_BYTES;
        if (s + 2 < G) load_stage(s + 2, cta, tid, sb);
#pragma unroll
        for (int ks = 0; ks < 4; ks++) {
            const int cur = ks & 1, nxt = cur ^ 1;
            if (ks < 3) {
                frag_load(Af[nxt], Bf[nxt], st, (ks + 1) * 32,
                          a_row_l, a_cb, b_row_l, b_cb);
            } else if (s + 1 < G) {
                if (s + 2 < G)
                    asm volatile("cp.async.wait_group 1;" ::: "memory");
                else
                    asm volatile("cp.async.wait_group 0;" ::: "memory");
                __syncthreads();
                frag_load(Af[nxt], Bf[nxt], sb + ((s + 1) % 3) * STAGE_BYTES, 0,
                          a_row_l, a_cb, b_row_l, b_cb);
            }
            do_mma(acc, Af[cur], Bf[cur]);
        }

        if ((s & (KTPT - 1)) == KTPT - 1) {
            // ---- epilogue for tile just finished (loads for next tile in flight) ----
            const int tile = cta + NCTA * (s >> 4);
            const int R = (tile >> 4) * BM;
            const int C = (tile & 15) * BNC;

            // in-register gates -> SA/SD
            {
                float bl_[2][2], bd_[2][2], bb_[2][2];
#pragma unroll
                for (int g = 0; g < 2; g++)
#pragma unroll
                    for (int e = 0; e < 2; e++) {
                        const int gc = C + wn * 16 + g * 8 + q2 + e;
                        bl_[g][e] = __ldg(pbl + gc);
                        bd_[g][e] = __ldg(pbd + gc);
                        bb_[g][e] = __ldg(pbb + gc);
                    }
#pragma unroll
                for (int mt = 0; mt < 2; mt++)
#pragma unroll
                    for (int h = 0; h < 2; h++) {
                        const int row = wm * 32 + mt * 16 + (lane >> 2) + 8 * h;
#pragma unroll
                        for (int g = 0; g < 2; g++) {
                            float a0, a1, d0, d1;
#pragma unroll
                            for (int e = 0; e < 2; e++) {
                                float lam = softplus_f(acc[mt][g][2 * h + e]     + bl_[g][e]);
                                float de  = softplus_f(acc[mt][2 + g][2 * h + e] + bd_[g][e]);
                                float u   = acc[mt][4 + g][2 * h + e] + bb_[g][e];
                                float al  = __expf(-de * lam);
                                float dr  = de * u;
                                if (e == 0) { a0 = al; d0 = dr; } else { a1 = al; d1 = dr; }
                            }
                            const int ch = wn * 16 + g * 8 + q2;
                            *(float2*)&SA[row * ASTR + ch] = make_float2(a0, a1);
                            *(float2*)&SD[row * ASTR + ch] = make_float2(d0, d1);
                        }
                    }
            }
            __syncthreads();

            // split scan: 128 threads, 2 per channel
            if (tid < 2 * BNC) {
                const int ch = tid & 63;
                const int hf = tid >> 6;
                float sc = 0.0f, P = 1.0f;
                const int t0 = hf * 64;
#pragma unroll 8
                for (int t = t0; t < t0 + 64; t++) {
                    float a = SA[t * ASTR + ch];
                    float d = SD[t * ASTR + ch];
                    sc = fmaf(a, sc, d);
                    P *= a;
                }
                sP[hf][ch] = P;
                sS[hf][ch] = sc;
            }
            __syncthreads();
            if (tid < BNC) {
                const float P = sP[0][tid] * sP[1][tid];
                const float sc = fmaf(sP[1][tid], sS[0][tid], sS[1][tid]);
                const int bidx = R >> 12;
                const int chunk = (R >> 7) & 31;
                const int idx = ((bidx * NCHUNK + chunk) << 10) + C + tid;
                g_P[idx] = P;
                g_S[idx] = sc;
            }

            // reset accumulators for next tile
#pragma unroll
            for (int i = 0; i < 2; i++)
#pragma unroll
                for (int j = 0; j < 6; j++)
#pragma unroll
                    for (int k = 0; k < 4; k++) acc[i][j][k] = 0.0f;
            __syncthreads();   // scan reads done before next tile's gates rewrite SA/SD
        }
    }
}

// ---------------- combine chunks + head projections ----------------
__global__ void __launch_bounds__(1024)
combine_kernel(const float* __restrict__ W_par, const float* __restrict__ b_par,
               const float* __restrict__ W_add, const float* __restrict__ b_add,
               float* __restrict__ out)
{
    const int b = blockIdx.x;
    const int d = threadIdx.x;

    float s = 0.0f;
#pragma unroll
    for (int c = 0; c < NCHUNK; c++) {
        const int idx = ((b * NCHUNK + c) << 10) + d;
        s = fmaf(g_P[idx], s, g_S[idx]);
    }

    float v0 = s * W_par[2 * d];
    float v1 = s * W_par[2 * d + 1];
    float v2 = s * W_add[d];

#pragma unroll
    for (int o = 16; o > 0; o >>= 1) {
        v0 += __shfl_xor_sync(0xffffffffu, v0, o);
        v1 += __shfl_xor_sync(0xffffffffu, v1, o);
        v2 += __shfl_xor_sync(0xffffffffu, v2, o);
    }

    __shared__ float r0[32], r1[32], r2[32];
    const int lane = d & 31, wid = d >> 5;
    if (lane == 0) { r0[wid] = v0; r1[wid] = v1; r2[wid] = v2; }
    __syncthreads();
    if (wid == 0) {
        v0 = r0[lane]; v1 = r1[lane]; v2 = r2[lane];
#pragma unroll
        for (int o = 16; o > 0; o >>= 1) {
            v0 += __shfl_xor_sync(0xffffffffu, v0, o);
            v1 += __shfl_xor_sync(0xffffffffu, v1, o);
            v2 += __shfl_xor_sync(0xffffffffu, v2, o);
        }
        if (lane == 0) {
            out[2 * b]     = v0 + b_par[0];
            out[2 * b + 1] = v1 + b_par[1];
            out[16 + b]    = v2 + b_add[0];
        }
    }
}

extern "C" void kernel_launch(void* const* d_in, const int* in_sizes, int n_in,
                              void* d_out, int out_size)
{
    const float* x  = (const float*)d_in[0];
    const float* Wl = (const float*)d_in[1];
    const float* bl = (const float*)d_in[2];
    const float* Wd = (const float*)d_in[3];
    const float* bd = (const float*)d_in[4];
    const float* Wb = (const float*)d_in[5];
    const float* bb = (const float*)d_in[6];
    const float* Wp = (const float*)d_in[7];
    const float* bp = (const float*)d_in[8];
    const float* Wa = (const float*)d_in[9];
    const float* ba = (const float*)d_in[10];
    float* out = (float*)d_out;

    cudaFuncSetAttribute(mamba_gemm_mma,
                         cudaFuncAttributeMaxDynamicSharedMemorySize, SMEM_TOTAL);

    conv_x_kernel<<<32768, 256>>>(x);
    conv_w_kernel<<<dim3(32, 32, 3), dim3(32, 8)>>>(Wl, Wd, Wb);
    mamba_gemm_mma<<<NCTA, NTH, SMEM_TOTAL>>>(bl, bd, bb);
    combine_kernel<<<8, 1024>>>(Wp, bp, Wa, ba, out);
}